// round 12
// baseline (speedup 1.0000x reference)
#include <cuda_runtime.h>
#include <cuda_fp16.h>

namespace {

constexpr int N  = 50000;
constexpr int E  = 1600000;
constexpr int IN = 512;
constexpr int H  = 128;
constexpr int C  = 2;
constexpr int G  = 8;
constexpr int NB_SCAN = (N + 255) / 256;

// ---- scratch (static device arrays; zero-initialized at load) ----
__device__ __half g_xh [(size_t)N * IN];  // x converted to fp16
__device__ __half g_w1t[(size_t)H * IN];  // W1^T fp16: [n][k]
__device__ __half g_w2t[(size_t)H * H];   // W2^T fp16: [n][k]
__device__ __half g_hs [(size_t)N * H];   // raw gemm output (UNscaled), fp16
__device__ __half g_hf [(size_t)N * H];   // layer-1 output (post agg+relu), fp16
__device__ float  g_dinv[N];
__device__ int    g_cnt [N];
__device__ int    g_incl[N];
__device__ int    g_bsum[256];
__device__ int    g_boff[256];
__device__ int    g_rowptr[N + 1];
__device__ int    g_cursor[N];
__device__ int2   g_adjp[E];              // {src, bits(dinv[src])} grouped by dst
__device__ float  g_pool[G * H];
__device__ float  g_cntf[G];

// ======================= input conversion =======================

__global__ void cvt_x_kernel(const float* __restrict__ x) {
    int i = blockIdx.x * blockDim.x + threadIdx.x;   // float4 index
    if (i >= N * IN / 4) return;
    float4 v = reinterpret_cast<const float4*>(x)[i];
    __half2 h0 = __floats2half2_rn(v.x, v.y);
    __half2 h1 = __floats2half2_rn(v.z, v.w);
    uint2 u;
    u.x = *reinterpret_cast<unsigned*>(&h0);
    u.y = *reinterpret_cast<unsigned*>(&h1);
    reinterpret_cast<uint2*>(g_xh)[i] = u;
}

__global__ void cvt_w_kernel(const float* __restrict__ W1, const float* __restrict__ W2) {
    int i = blockIdx.x * blockDim.x + threadIdx.x;
    if (i < H * IN) {
        int n = i >> 9, k = i & (IN - 1);
        g_w1t[i] = __float2half(W1[k * H + n]);
    } else if (i < H * IN + H * H) {
        int j = i - H * IN;
        int n = j >> 7, k = j & (H - 1);
        g_w2t[j] = __float2half(W2[k * H + n]);
    }
}

// ======================= CSR build =======================

__global__ void count_kernel(const int* __restrict__ dst) {
    int e = blockIdx.x * blockDim.x + threadIdx.x;
    if (e < E) atomicAdd(&g_cnt[dst[e]], 1);
}

__global__ void scanA_kernel() {
    __shared__ int sm[256];
    int t = threadIdx.x;
    int i = blockIdx.x * 256 + t;
    int v = (i < N) ? g_cnt[i] : 0;
    sm[t] = v;
    __syncthreads();
    #pragma unroll
    for (int off = 1; off < 256; off <<= 1) {
        int u = (t >= off) ? sm[t - off] : 0;
        __syncthreads();
        sm[t] += u;
        __syncthreads();
    }
    if (i < N) g_incl[i] = sm[t];
    if (t == 255) g_bsum[blockIdx.x] = sm[255];
}

__global__ void scanB_kernel() {
    __shared__ int sm[256];
    int t = threadIdx.x;
    int v = (t < NB_SCAN) ? g_bsum[t] : 0;
    sm[t] = v;
    __syncthreads();
    #pragma unroll
    for (int off = 1; off < 256; off <<= 1) {
        int u = (t >= off) ? sm[t - off] : 0;
        __syncthreads();
        sm[t] += u;
        __syncthreads();
    }
    g_boff[t] = sm[t] - v;   // exclusive
}

__global__ void scanCD_kernel() {
    int i = blockIdx.x * blockDim.x + threadIdx.x;
    if (i < N) {
        int c = g_cnt[i];
        int inc = g_incl[i] + g_boff[i >> 8];
        g_rowptr[i + 1] = inc;
        g_cursor[i] = inc - c;
        g_dinv[i] = rsqrtf((float)c + 1.0f);
        g_cnt[i] = 0;
        if (i == 0) g_rowptr[0] = 0;
    }
}

__global__ void fill_kernel(const int* __restrict__ src, const int* __restrict__ dst) {
    int e = blockIdx.x * blockDim.x + threadIdx.x;
    if (e < E) {
        int s = src[e];
        int d = dst[e];
        int pos = atomicAdd(&g_cursor[d], 1);
        g_adjp[pos] = make_int2(s, __float_as_int(g_dinv[s]));
    }
}

__global__ void zero_pool_kernel() {
    int i = blockIdx.x * blockDim.x + threadIdx.x;
    if (i < G * H) g_pool[i] = 0.f;
    if (i < G) g_cntf[i] = 0.f;
}

// ======================= fp16 tensor-core GEMM =======================
// hs[r, 0:128] = half( A[r,:] @ Wt^T )  where A fp16 [M,K], Wt fp16 [128][K].
// Block 128x128, 8 warps (4 wm x 2 wn), warp tile 32x64, BK=64 (4 k16-steps),
// 3-stage cp.async ring, ldmatrix fragment loads, m16n8k16 f16 mma.

__device__ __forceinline__ void mma_f16(float* d, const unsigned* a, const unsigned* b) {
    asm volatile("mma.sync.aligned.m16n8k16.row.col.f32.f16.f16.f32 "
        "{%0,%1,%2,%3}, {%4,%5,%6,%7}, {%8,%9}, {%0,%1,%2,%3};"
        : "+f"(d[0]), "+f"(d[1]), "+f"(d[2]), "+f"(d[3])
        : "r"(a[0]), "r"(a[1]), "r"(a[2]), "r"(a[3]), "r"(b[0]), "r"(b[1]));
}

__device__ __forceinline__ void ldsm4(unsigned& r0, unsigned& r1, unsigned& r2, unsigned& r3,
                                      unsigned addr) {
    asm volatile("ldmatrix.sync.aligned.m8n8.x4.shared.b16 {%0,%1,%2,%3}, [%4];"
                 : "=r"(r0), "=r"(r1), "=r"(r2), "=r"(r3) : "r"(addr));
}

__device__ __forceinline__ void cp16(void* smem_dst, const void* gmem_src, int src_bytes) {
    unsigned sa = (unsigned)__cvta_generic_to_shared(smem_dst);
    asm volatile("cp.async.cg.shared.global [%0], [%1], 16, %2;"
                 :: "r"(sa), "l"(gmem_src), "r"(src_bytes) : "memory");
}
__device__ __forceinline__ void cp_commit() {
    asm volatile("cp.async.commit_group;" ::: "memory");
}
template <int Nw>
__device__ __forceinline__ void cp_wait() {
    asm volatile("cp.async.wait_group %0;" :: "n"(Nw) : "memory");
}

constexpr int BK = 64;
constexpr int ROWB = 144;                  // 72 halfs per padded row (64 + 8)
constexpr int A_STG = 128 * ROWB;          // bytes per A stage
constexpr int B_STG = 128 * ROWB;          // bytes per B stage
constexpr size_t GEMM_SMEM = 3 * (size_t)(A_STG + B_STG);   // 110592 B

template <int K>
__global__ void __launch_bounds__(256, 2)
gemm_f16(const __half* __restrict__ A, const __half* __restrict__ Wt,
         __half* __restrict__ hs) {
    constexpr int STAGES = K / BK;

    extern __shared__ char smem[];
    const unsigned sbase = (unsigned)__cvta_generic_to_shared(smem);

    const int tid  = threadIdx.x;
    const int lane = tid & 31;
    const int wid  = tid >> 5;
    const int wm   = wid >> 1;      // 0..3, 32 rows
    const int wn   = wid & 1;       // 0..1, 64 cols
    const int bm   = blockIdx.x * 128;

    auto issue = [&](int s) {
        const int buf = s % 3;
        const int k0 = s * BK;
        {   // A: 128 rows x 128 B
            int r = tid >> 1;
            int gr = bm + r;
            int sz = (gr < N) ? 16 : 0;
            const __half* srow = A + (size_t)gr * K + k0;
            char* dst = smem + buf * A_STG + r * ROWB;
            #pragma unroll
            for (int j = 0; j < 4; j++) {
                int ch = (tid & 1) + 2 * j;
                cp16(dst + ch * 16, srow + ch * 8, sz);
            }
        }
        {   // B: 128 n-rows x 128 B
            int n = tid >> 1;
            const __half* srow = Wt + (size_t)n * K + k0;
            char* dst = smem + 3 * A_STG + buf * B_STG + n * ROWB;
            #pragma unroll
            for (int j = 0; j < 4; j++) {
                int ch = (tid & 1) + 2 * j;
                cp16(dst + ch * 16, srow + ch * 8, 16);
            }
        }
        cp_commit();
    };

    float acc[2][8][4];
    #pragma unroll
    for (int i = 0; i < 2; i++)
        #pragma unroll
        for (int j = 0; j < 8; j++)
            #pragma unroll
            for (int r = 0; r < 4; r++) acc[i][j][r] = 0.f;

    const int sub = lane >> 3;     // ldmatrix group 0..3
    const int r8  = lane & 7;

    auto compute = [&](int s) {
        const int buf = s % 3;
        const unsigned abase = sbase + buf * A_STG;
        const unsigned bbase = sbase + 3 * A_STG + buf * B_STG;
        #pragma unroll
        for (int ks = 0; ks < 4; ks++) {
            const int kcol = ks * 16;
            unsigned af[2][4];
            #pragma unroll
            for (int mt = 0; mt < 2; mt++) {
                int row = wm * 32 + mt * 16 + r8 + (sub & 1) * 8;
                int col = kcol + (sub >> 1) * 8;
                ldsm4(af[mt][0], af[mt][1], af[mt][2], af[mt][3],
                      abase + row * ROWB + col * 2);
            }
            unsigned bf[8][2];
            #pragma unroll
            for (int pr = 0; pr < 4; pr++) {
                int row = wn * 64 + pr * 16 + r8 + (sub >> 1) * 8;
                int col = kcol + (sub & 1) * 8;
                ldsm4(bf[2 * pr][0], bf[2 * pr][1], bf[2 * pr + 1][0], bf[2 * pr + 1][1],
                      bbase + row * ROWB + col * 2);
            }
            #pragma unroll
            for (int mt = 0; mt < 2; mt++)
                #pragma unroll
                for (int nt = 0; nt < 8; nt++)
                    mma_f16(acc[mt][nt], af[mt], bf[nt]);
        }
    };

    issue(0);
    if (STAGES > 1) issue(1);
    for (int s = 0; s < STAGES; s++) {
        if (s + 2 < STAGES) cp_wait<1>(); else cp_wait<0>();
        __syncthreads();
        if (s + 2 < STAGES) issue(s + 2);
        compute(s);
    }

    const int gid = lane >> 2;
    const int cid = lane & 3;
    #pragma unroll
    for (int mt = 0; mt < 2; mt++) {
        #pragma unroll
        for (int half = 0; half < 2; half++) {
            int r = bm + wm * 32 + mt * 16 + gid + half * 8;
            if (r < N) {
                #pragma unroll
                for (int nt = 0; nt < 8; nt++) {
                    int c = wn * 64 + nt * 8 + cid * 2;
                    __half2 v = __floats2half2_rn(acc[mt][nt][half * 2],
                                                  acc[mt][nt][half * 2 + 1]);
                    *reinterpret_cast<__half2*>(hs + (size_t)r * H + c) = v;
                }
            }
        }
    }
}

// ======================= CSR aggregation =======================

__device__ __forceinline__ void acc_row(float4& acc, uint2 u, float sc) {
    float2 f0 = __half22float2(*reinterpret_cast<__half2*>(&u.x));
    float2 f1 = __half22float2(*reinterpret_cast<__half2*>(&u.y));
    acc.x = fmaf(f0.x, sc, acc.x);
    acc.y = fmaf(f0.y, sc, acc.y);
    acc.z = fmaf(f1.x, sc, acc.z);
    acc.w = fmaf(f1.y, sc, acc.w);
}

__device__ __forceinline__ float4 node_row(const uint2* hs2, const float* bias,
                                           int w, int lane) {
    int beg = __ldg(&g_rowptr[w]);
    int end = __ldg(&g_rowptr[w + 1]);
    float di = g_dinv[w];

    float4 acc = make_float4(0.f, 0.f, 0.f, 0.f);
    acc_row(acc, __ldg(&hs2[(size_t)w * 32 + lane]), di);   // self term

    int e = beg;
    for (; e + 8 <= end; e += 8) {
        int2 p[8];
        #pragma unroll
        for (int j = 0; j < 8; j++) p[j] = __ldg(&g_adjp[e + j]);
        uint2 v[8];
        #pragma unroll
        for (int j = 0; j < 8; j++) v[j] = __ldg(&hs2[(size_t)p[j].x * 32 + lane]);
        #pragma unroll
        for (int j = 0; j < 8; j++) acc_row(acc, v[j], __int_as_float(p[j].y));
    }
    for (; e < end; e++) {
        int2 p = __ldg(&g_adjp[e]);
        acc_row(acc, __ldg(&hs2[(size_t)p.x * 32 + lane]), __int_as_float(p.y));
    }

    float4 bb = __ldg(&reinterpret_cast<const float4*>(bias)[lane]);
    float4 r;
    r.x = fmaxf(fmaf(di, acc.x, bb.x), 0.f);
    r.y = fmaxf(fmaf(di, acc.y, bb.y), 0.f);
    r.z = fmaxf(fmaf(di, acc.z, bb.z), 0.f);
    r.w = fmaxf(fmaf(di, acc.w, bb.w), 0.f);
    return r;
}

// Layer 1: write h rows as fp16 (feeds gemm2 directly).
__global__ void __launch_bounds__(256)
agg_kernel(const __half* __restrict__ hs, const float* __restrict__ bias,
           __half* __restrict__ hf) {
    int w = (blockIdx.x * 256 + threadIdx.x) >> 5;
    if (w >= N) return;
    int lane = threadIdx.x & 31;
    float4 r = node_row(reinterpret_cast<const uint2*>(hs), bias, w, lane);
    __half2 h0 = __floats2half2_rn(r.x, r.y);
    __half2 h1 = __floats2half2_rn(r.z, r.w);
    uint2 u;
    u.x = *reinterpret_cast<unsigned*>(&h0);
    u.y = *reinterpret_cast<unsigned*>(&h1);
    reinterpret_cast<uint2*>(hf)[(size_t)w * 32 + lane] = u;
}

// Layer 2 fused with global mean pool.
__global__ void __launch_bounds__(256)
agg_pool_kernel(const __half* __restrict__ hs, const float* __restrict__ bias,
                const int* __restrict__ batch) {
    __shared__ float accsm[G * H];
    __shared__ float cntsm[G];
    int tid = threadIdx.x;
    for (int i = tid; i < G * H; i += 256) accsm[i] = 0.f;
    if (tid < G) cntsm[tid] = 0.f;
    __syncthreads();

    int w = (blockIdx.x * 256 + tid) >> 5;
    int lane = tid & 31;
    float4 r = node_row(reinterpret_cast<const uint2*>(hs), bias, w, lane);

    int g = __ldg(&batch[w]);
    atomicAdd(&accsm[g * H + lane * 4 + 0], r.x);
    atomicAdd(&accsm[g * H + lane * 4 + 1], r.y);
    atomicAdd(&accsm[g * H + lane * 4 + 2], r.z);
    atomicAdd(&accsm[g * H + lane * 4 + 3], r.w);
    if (lane == 0) atomicAdd(&cntsm[g], 1.0f);
    __syncthreads();

    for (int i = tid; i < G * H; i += 256)
        if (accsm[i] != 0.f) atomicAdd(&g_pool[i], accsm[i]);
    if (tid < G && cntsm[tid] != 0.f) atomicAdd(&g_cntf[tid], cntsm[tid]);
}

// ======================= head =======================

__global__ void head_kernel(const float* __restrict__ Wlin, const float* __restrict__ blin,
                            float* __restrict__ out) {
    int warp = threadIdx.x >> 5, lane = threadIdx.x & 31;
    if (warp >= G * C) return;
    int g = warp >> 1, c = warp & 1;
    float s = 0.f;
    for (int d = lane; d < H; d += 32)
        s += g_pool[g * H + d] * Wlin[d * C + c];
    #pragma unroll
    for (int o = 16; o; o >>= 1) s += __shfl_xor_sync(0xffffffff, s, o);
    if (lane == 0) out[g * C + c] = s / fmaxf(g_cntf[g], 1.0f) + blin[c];
}

} // namespace

extern "C" void kernel_launch(void* const* d_in, const int* in_sizes, int n_in,
                              void* d_out, int out_size) {
    const float* x    = (const float*)d_in[0];
    const int*   ei   = (const int*)  d_in[1];
    const int*   bat  = (const int*)  d_in[2];
    const float* W1   = (const float*)d_in[3];
    const float* b1   = (const float*)d_in[4];
    const float* W2   = (const float*)d_in[5];
    const float* b2   = (const float*)d_in[6];
    const float* Wlin = (const float*)d_in[7];
    const float* blin = (const float*)d_in[8];
    float* out = (float*)d_out;
    const int* src = ei;
    const int* dst = ei + E;

    __half *p_xh, *p_w1t, *p_w2t, *p_hs, *p_hf;
    cudaGetSymbolAddress((void**)&p_xh,  g_xh);
    cudaGetSymbolAddress((void**)&p_w1t, g_w1t);
    cudaGetSymbolAddress((void**)&p_w2t, g_w2t);
    cudaGetSymbolAddress((void**)&p_hs,  g_hs);
    cudaGetSymbolAddress((void**)&p_hf,  g_hf);

    cudaFuncSetAttribute(gemm_f16<IN>, cudaFuncAttributeMaxDynamicSharedMemorySize, (int)GEMM_SMEM);
    cudaFuncSetAttribute(gemm_f16<H>,  cudaFuncAttributeMaxDynamicSharedMemorySize, (int)GEMM_SMEM);

    static cudaStream_t s2 = nullptr;
    static cudaEvent_t ev_fork = nullptr, ev_join = nullptr;
    if (!s2) {
        cudaStreamCreateWithFlags(&s2, cudaStreamNonBlocking);
        cudaEventCreateWithFlags(&ev_fork, cudaEventDisableTiming);
        cudaEventCreateWithFlags(&ev_join, cudaEventDisableTiming);
    }

    const int gemm_grid = (N + 127) / 128;       // 391
    const int agg_grid  = (N * 32) / 256;        // 6250
    const int nthr_grid = (N + 255) / 256;
    const int e_grid    = (E + 255) / 256;
    const int cvtx_grid = (N * IN / 4 + 255) / 256;
    const int cvtw_grid = (H * IN + H * H + 255) / 256;

    // ---- fork: CSR build on side stream; convert + gemm1 on main ----
    cudaEventRecord(ev_fork, 0);
    cudaStreamWaitEvent(s2, ev_fork, 0);

    count_kernel<<<e_grid, 256, 0, s2>>>(dst);                     // 0
    cvt_w_kernel<<<cvtw_grid, 256>>>(W1, W2);                      // 1 (main)
    cvt_x_kernel<<<cvtx_grid, 256>>>(x);                           // 2 (main)
    gemm_f16<IN><<<gemm_grid, 256, GEMM_SMEM>>>(p_xh, p_w1t, p_hs); // 3 (main, ncu)
    scanA_kernel<<<NB_SCAN, 256, 0, s2>>>();                       // 4
    scanB_kernel<<<1, 256, 0, s2>>>();                             // 5
    scanCD_kernel<<<nthr_grid, 256, 0, s2>>>();                    // 6
    fill_kernel<<<e_grid, 256, 0, s2>>>(src, dst);                 // 7
    zero_pool_kernel<<<(G * H + 255) / 256, 256, 0, s2>>>();       // 8
    cudaEventRecord(ev_join, s2);

    // ---- join ----
    cudaStreamWaitEvent(0, ev_join, 0);

    // ---- layer 1 agg (fp16 out), layer 2, fused pool, head ----
    agg_kernel<<<agg_grid, 256>>>(p_hs, b1, p_hf);
    gemm_f16<H><<<gemm_grid, 256, GEMM_SMEM>>>(p_hf, p_w2t, p_hs);
    agg_pool_kernel<<<agg_grid, 256>>>(p_hs, b2, bat);
    head_kernel<<<1, G * C * 32>>>(Wlin, blin, out);
}

// round 13
// speedup vs baseline: 1.0594x; 1.0594x over previous
#include <cuda_runtime.h>
#include <cuda_fp16.h>

namespace {

constexpr int N  = 50000;
constexpr int E  = 1600000;
constexpr int IN = 512;
constexpr int H  = 128;
constexpr int C  = 2;
constexpr int G  = 8;
constexpr int NB_SCAN = (N + 255) / 256;

// ---- scratch (static device arrays; zero-initialized at load) ----
__device__ __half g_w2t[(size_t)H * H];   // W2^T fp16: [n][k]
__device__ __half g_hs [(size_t)N * H];   // raw gemm output (UNscaled), fp16
__device__ __half g_hf [(size_t)N * H];   // layer-1 output (post agg+relu), fp16
__device__ float  g_dinv[N];
__device__ int    g_cnt [N];
__device__ int    g_incl[N];
__device__ int    g_bsum[256];
__device__ int    g_boff[256];
__device__ int    g_rowptr[N + 1];
__device__ int    g_cursor[N];
__device__ int2   g_adjp[E];              // {src, bits(dinv[src])} grouped by dst
__device__ float  g_pool[G * H];
__device__ float  g_cntf[G];

// ======================= small conversions =======================

__global__ void cvt_w2_kernel(const float* __restrict__ W2) {
    int i = blockIdx.x * blockDim.x + threadIdx.x;
    if (i < H * H) {
        int n = i >> 7, k = i & (H - 1);
        g_w2t[i] = __float2half(W2[k * H + n]);
    }
}

// ======================= CSR build =======================

__global__ void count_kernel(const int* __restrict__ dst) {
    int e = blockIdx.x * blockDim.x + threadIdx.x;
    if (e < E) atomicAdd(&g_cnt[dst[e]], 1);
}

__global__ void scanA_kernel() {
    __shared__ int sm[256];
    int t = threadIdx.x;
    int i = blockIdx.x * 256 + t;
    int v = (i < N) ? g_cnt[i] : 0;
    sm[t] = v;
    __syncthreads();
    #pragma unroll
    for (int off = 1; off < 256; off <<= 1) {
        int u = (t >= off) ? sm[t - off] : 0;
        __syncthreads();
        sm[t] += u;
        __syncthreads();
    }
    if (i < N) g_incl[i] = sm[t];
    if (t == 255) g_bsum[blockIdx.x] = sm[255];
}

__global__ void scanB_kernel() {
    __shared__ int sm[256];
    int t = threadIdx.x;
    int v = (t < NB_SCAN) ? g_bsum[t] : 0;
    sm[t] = v;
    __syncthreads();
    #pragma unroll
    for (int off = 1; off < 256; off <<= 1) {
        int u = (t >= off) ? sm[t - off] : 0;
        __syncthreads();
        sm[t] += u;
        __syncthreads();
    }
    g_boff[t] = sm[t] - v;   // exclusive
}

__global__ void scanCD_kernel() {
    int i = blockIdx.x * blockDim.x + threadIdx.x;
    if (i < N) {
        int c = g_cnt[i];
        int inc = g_incl[i] + g_boff[i >> 8];
        g_rowptr[i + 1] = inc;
        g_cursor[i] = inc - c;
        g_dinv[i] = rsqrtf((float)c + 1.0f);
        g_cnt[i] = 0;
        if (i == 0) g_rowptr[0] = 0;
    }
}

__global__ void fill_kernel(const int* __restrict__ src, const int* __restrict__ dst) {
    int e = blockIdx.x * blockDim.x + threadIdx.x;
    if (e < E) {
        int s = src[e];
        int d = dst[e];
        int pos = atomicAdd(&g_cursor[d], 1);
        g_adjp[pos] = make_int2(s, __float_as_int(g_dinv[s]));
    }
}

__global__ void zero_pool_kernel() {
    int i = blockIdx.x * blockDim.x + threadIdx.x;
    if (i < G * H) g_pool[i] = 0.f;
    if (i < G) g_cntf[i] = 0.f;
}

// ======================= shared GEMM plumbing =======================

__device__ __forceinline__ void cp16(void* smem_dst, const void* gmem_src, int src_bytes) {
    unsigned sa = (unsigned)__cvta_generic_to_shared(smem_dst);
    asm volatile("cp.async.cg.shared.global [%0], [%1], 16, %2;"
                 :: "r"(sa), "l"(gmem_src), "r"(src_bytes) : "memory");
}
__device__ __forceinline__ void cp_commit() {
    asm volatile("cp.async.commit_group;" ::: "memory");
}
template <int Nw>
__device__ __forceinline__ void cp_wait() {
    asm volatile("cp.async.wait_group %0;" :: "n"(Nw) : "memory");
}

// ======================= tf32 GEMM (layer 1: fp32 A input) =======================
// Block 128x128, 8 warps (4x2), warp tile 32x64, BK=32, 3-stage ring, 2 CTA/SM.

__device__ __forceinline__ void mma_tf32(float* d, const unsigned* a, const unsigned* b) {
    asm volatile("mma.sync.aligned.m16n8k8.row.col.f32.tf32.tf32.f32 "
        "{%0,%1,%2,%3}, {%4,%5,%6,%7}, {%8,%9}, {%0,%1,%2,%3};"
        : "+f"(d[0]), "+f"(d[1]), "+f"(d[2]), "+f"(d[3])
        : "r"(a[0]), "r"(a[1]), "r"(a[2]), "r"(a[3]), "r"(b[0]), "r"(b[1]));
}

__device__ __forceinline__ unsigned rtf(float f) {
    return __float_as_uint(f) + 0x1000u;   // rn-to-tf32 bit trick
}

constexpr int APAD = 36;
constexpr int BPAD = 136;
constexpr int ASTG = 128 * APAD;
constexpr int BSTG = 32 * BPAD;
constexpr size_t T32_SMEM = (size_t)(3 * ASTG + 3 * BSTG) * 4;   // 105 KB

template <int K>
__global__ void __launch_bounds__(256, 2)
gemm_t32(const float* __restrict__ A, const float* __restrict__ W,
         __half* __restrict__ hs) {
    constexpr int BK = 32;
    constexpr int STAGES = K / BK;

    extern __shared__ float smemf[];
    float* As = smemf;
    float* Bs = smemf + 3 * ASTG;

    const int tid  = threadIdx.x;
    const int lane = tid & 31;
    const int wid  = tid >> 5;
    const int wm   = wid >> 1;
    const int wn   = wid & 1;
    const int bm   = blockIdx.x * 128;

    auto AS = [&](int b, int r, int c) -> float& { return As[b * ASTG + r * APAD + c]; };
    auto BS = [&](int b, int k, int n) -> float& { return Bs[b * BSTG + k * BPAD + n]; };

    auto issue = [&](int s) {
        const int buf = s % 3;
        const int k0 = s * BK;
        {
            int r = tid >> 1;
            int gr = bm + r;
            int sz = (gr < N) ? 16 : 0;
            const float* srow = A + (size_t)gr * K + k0;
            #pragma unroll
            for (int j = 0; j < 4; j++) {
                int ch = (tid & 1) + 2 * j;
                cp16(&AS(buf, r, ch * 4), srow + ch * 4, sz);
            }
        }
        {
            int k = tid >> 3;
            const float* srow = W + (size_t)(k0 + k) * H;
            #pragma unroll
            for (int j = 0; j < 4; j++) {
                int ch = (tid & 7) + 8 * j;
                cp16(&BS(buf, k, ch * 4), srow + ch * 4, 16);
            }
        }
        cp_commit();
    };

    float acc[2][8][4];
    #pragma unroll
    for (int i = 0; i < 2; i++)
        #pragma unroll
        for (int j = 0; j < 8; j++)
            #pragma unroll
            for (int r = 0; r < 4; r++) acc[i][j][r] = 0.f;

    const int gid = lane >> 2;
    const int cid = lane & 3;

    auto compute = [&](int s) {
        const int buf = s % 3;
        #pragma unroll
        for (int ks = 0; ks < 4; ks++) {
            const int c0 = ks * 8 + cid;
            unsigned af[2][4];
            #pragma unroll
            for (int mt = 0; mt < 2; mt++) {
                int r = wm * 32 + mt * 16 + gid;
                af[mt][0] = rtf(AS(buf, r,     c0));
                af[mt][1] = rtf(AS(buf, r + 8, c0));
                af[mt][2] = rtf(AS(buf, r,     c0 + 4));
                af[mt][3] = rtf(AS(buf, r + 8, c0 + 4));
            }
            unsigned bf[8][2];
            #pragma unroll
            for (int nt = 0; nt < 8; nt++) {
                int n = wn * 64 + nt * 8 + gid;
                bf[nt][0] = rtf(BS(buf, ks * 8 + cid,     n));
                bf[nt][1] = rtf(BS(buf, ks * 8 + cid + 4, n));
            }
            #pragma unroll
            for (int mt = 0; mt < 2; mt++)
                #pragma unroll
                for (int nt = 0; nt < 8; nt++)
                    mma_tf32(acc[mt][nt], af[mt], bf[nt]);
        }
    };

    issue(0);
    if (STAGES > 1) issue(1);
    for (int s = 0; s < STAGES; s++) {
        if (s + 2 < STAGES) cp_wait<1>(); else cp_wait<0>();
        __syncthreads();
        if (s + 2 < STAGES) issue(s + 2);
        compute(s);
    }

    #pragma unroll
    for (int mt = 0; mt < 2; mt++) {
        #pragma unroll
        for (int half = 0; half < 2; half++) {
            int r = bm + wm * 32 + mt * 16 + gid + half * 8;
            if (r < N) {
                #pragma unroll
                for (int nt = 0; nt < 8; nt++) {
                    int c = wn * 64 + nt * 8 + cid * 2;
                    __half2 v = __floats2half2_rn(acc[mt][nt][half * 2],
                                                  acc[mt][nt][half * 2 + 1]);
                    *reinterpret_cast<__half2*>(hs + (size_t)r * H + c) = v;
                }
            }
        }
    }
}

// ======================= fp16 GEMM (layer 2: fp16 A input) =======================
// Block 128x128, 8 warps, warp tile 32x64, BK=64, ldmatrix + m16n8k16.

__device__ __forceinline__ void mma_f16(float* d, const unsigned* a, const unsigned* b) {
    asm volatile("mma.sync.aligned.m16n8k16.row.col.f32.f16.f16.f32 "
        "{%0,%1,%2,%3}, {%4,%5,%6,%7}, {%8,%9}, {%0,%1,%2,%3};"
        : "+f"(d[0]), "+f"(d[1]), "+f"(d[2]), "+f"(d[3])
        : "r"(a[0]), "r"(a[1]), "r"(a[2]), "r"(a[3]), "r"(b[0]), "r"(b[1]));
}

__device__ __forceinline__ void ldsm4(unsigned& r0, unsigned& r1, unsigned& r2, unsigned& r3,
                                      unsigned addr) {
    asm volatile("ldmatrix.sync.aligned.m8n8.x4.shared.b16 {%0,%1,%2,%3}, [%4];"
                 : "=r"(r0), "=r"(r1), "=r"(r2), "=r"(r3) : "r"(addr));
}

constexpr int F_BK = 64;
constexpr int ROWB = 144;                  // 72 halfs per padded row
constexpr int FA_STG = 128 * ROWB;
constexpr int FB_STG = 128 * ROWB;
constexpr size_t F16_SMEM = 3 * (size_t)(FA_STG + FB_STG);   // 110592 B

template <int K>
__global__ void __launch_bounds__(256, 2)
gemm_f16(const __half* __restrict__ A, const __half* __restrict__ Wt,
         __half* __restrict__ hs) {
    constexpr int STAGES = K / F_BK;

    extern __shared__ char smem[];
    const unsigned sbase = (unsigned)__cvta_generic_to_shared(smem);

    const int tid  = threadIdx.x;
    const int lane = tid & 31;
    const int wid  = tid >> 5;
    const int wm   = wid >> 1;
    const int wn   = wid & 1;
    const int bm   = blockIdx.x * 128;

    auto issue = [&](int s) {
        const int buf = s % 3;
        const int k0 = s * F_BK;
        {
            int r = tid >> 1;
            int gr = bm + r;
            int sz = (gr < N) ? 16 : 0;
            const __half* srow = A + (size_t)gr * K + k0;
            char* dst = smem + buf * FA_STG + r * ROWB;
            #pragma unroll
            for (int j = 0; j < 4; j++) {
                int ch = (tid & 1) + 2 * j;
                cp16(dst + ch * 16, srow + ch * 8, sz);
            }
        }
        {
            int n = tid >> 1;
            const __half* srow = Wt + (size_t)n * K + k0;
            char* dst = smem + 3 * FA_STG + buf * FB_STG + n * ROWB;
            #pragma unroll
            for (int j = 0; j < 4; j++) {
                int ch = (tid & 1) + 2 * j;
                cp16(dst + ch * 16, srow + ch * 8, 16);
            }
        }
        cp_commit();
    };

    float acc[2][8][4];
    #pragma unroll
    for (int i = 0; i < 2; i++)
        #pragma unroll
        for (int j = 0; j < 8; j++)
            #pragma unroll
            for (int r = 0; r < 4; r++) acc[i][j][r] = 0.f;

    const int sub = lane >> 3;
    const int r8  = lane & 7;

    auto compute = [&](int s) {
        const int buf = s % 3;
        const unsigned abase = sbase + buf * FA_STG;
        const unsigned bbase = sbase + 3 * FA_STG + buf * FB_STG;
        #pragma unroll
        for (int ks = 0; ks < 4; ks++) {
            const int kcol = ks * 16;
            unsigned af[2][4];
            #pragma unroll
            for (int mt = 0; mt < 2; mt++) {
                int row = wm * 32 + mt * 16 + r8 + (sub & 1) * 8;
                int col = kcol + (sub >> 1) * 8;
                ldsm4(af[mt][0], af[mt][1], af[mt][2], af[mt][3],
                      abase + row * ROWB + col * 2);
            }
            unsigned bf[8][2];
            #pragma unroll
            for (int pr = 0; pr < 4; pr++) {
                int row = wn * 64 + pr * 16 + r8 + (sub >> 1) * 8;
                int col = kcol + (sub & 1) * 8;
                ldsm4(bf[2 * pr][0], bf[2 * pr][1], bf[2 * pr + 1][0], bf[2 * pr + 1][1],
                      bbase + row * ROWB + col * 2);
            }
            #pragma unroll
            for (int mt = 0; mt < 2; mt++)
                #pragma unroll
                for (int nt = 0; nt < 8; nt++)
                    mma_f16(acc[mt][nt], af[mt], bf[nt]);
        }
    };

    issue(0);
    if (STAGES > 1) issue(1);
    for (int s = 0; s < STAGES; s++) {
        if (s + 2 < STAGES) cp_wait<1>(); else cp_wait<0>();
        __syncthreads();
        if (s + 2 < STAGES) issue(s + 2);
        compute(s);
    }

    const int gid = lane >> 2;
    const int cid = lane & 3;
    #pragma unroll
    for (int mt = 0; mt < 2; mt++) {
        #pragma unroll
        for (int half = 0; half < 2; half++) {
            int r = bm + wm * 32 + mt * 16 + gid + half * 8;
            if (r < N) {
                #pragma unroll
                for (int nt = 0; nt < 8; nt++) {
                    int c = wn * 64 + nt * 8 + cid * 2;
                    __half2 v = __floats2half2_rn(acc[mt][nt][half * 2],
                                                  acc[mt][nt][half * 2 + 1]);
                    *reinterpret_cast<__half2*>(hs + (size_t)r * H + c) = v;
                }
            }
        }
    }
}

// ======================= CSR aggregation =======================

__device__ __forceinline__ void acc_row(float4& acc, uint2 u, float sc) {
    float2 f0 = __half22float2(*reinterpret_cast<__half2*>(&u.x));
    float2 f1 = __half22float2(*reinterpret_cast<__half2*>(&u.y));
    acc.x = fmaf(f0.x, sc, acc.x);
    acc.y = fmaf(f0.y, sc, acc.y);
    acc.z = fmaf(f1.x, sc, acc.z);
    acc.w = fmaf(f1.y, sc, acc.w);
}

__device__ __forceinline__ float4 node_row(const uint2* hs2, const float* bias,
                                           int w, int lane) {
    int beg = __ldg(&g_rowptr[w]);
    int end = __ldg(&g_rowptr[w + 1]);
    float di = g_dinv[w];

    float4 acc = make_float4(0.f, 0.f, 0.f, 0.f);
    acc_row(acc, __ldg(&hs2[(size_t)w * 32 + lane]), di);   // self term

    int e = beg;
    for (; e + 8 <= end; e += 8) {
        int2 p[8];
        #pragma unroll
        for (int j = 0; j < 8; j++) p[j] = __ldg(&g_adjp[e + j]);
        uint2 v[8];
        #pragma unroll
        for (int j = 0; j < 8; j++) v[j] = __ldg(&hs2[(size_t)p[j].x * 32 + lane]);
        #pragma unroll
        for (int j = 0; j < 8; j++) acc_row(acc, v[j], __int_as_float(p[j].y));
    }
    for (; e < end; e++) {
        int2 p = __ldg(&g_adjp[e]);
        acc_row(acc, __ldg(&hs2[(size_t)p.x * 32 + lane]), __int_as_float(p.y));
    }

    float4 bb = __ldg(&reinterpret_cast<const float4*>(bias)[lane]);
    float4 r;
    r.x = fmaxf(fmaf(di, acc.x, bb.x), 0.f);
    r.y = fmaxf(fmaf(di, acc.y, bb.y), 0.f);
    r.z = fmaxf(fmaf(di, acc.z, bb.z), 0.f);
    r.w = fmaxf(fmaf(di, acc.w, bb.w), 0.f);
    return r;
}

// Layer 1: write h rows as fp16 (feeds gemm2 directly).
__global__ void __launch_bounds__(256)
agg_kernel(const __half* __restrict__ hs, const float* __restrict__ bias,
           __half* __restrict__ hf) {
    int w = (blockIdx.x * 256 + threadIdx.x) >> 5;
    if (w >= N) return;
    int lane = threadIdx.x & 31;
    float4 r = node_row(reinterpret_cast<const uint2*>(hs), bias, w, lane);
    __half2 h0 = __floats2half2_rn(r.x, r.y);
    __half2 h1 = __floats2half2_rn(r.z, r.w);
    uint2 u;
    u.x = *reinterpret_cast<unsigned*>(&h0);
    u.y = *reinterpret_cast<unsigned*>(&h1);
    reinterpret_cast<uint2*>(hf)[(size_t)w * 32 + lane] = u;
}

// Layer 2 fused with global mean pool.
__global__ void __launch_bounds__(256)
agg_pool_kernel(const __half* __restrict__ hs, const float* __restrict__ bias,
                const int* __restrict__ batch) {
    __shared__ float accsm[G * H];
    __shared__ float cntsm[G];
    int tid = threadIdx.x;
    for (int i = tid; i < G * H; i += 256) accsm[i] = 0.f;
    if (tid < G) cntsm[tid] = 0.f;
    __syncthreads();

    int w = (blockIdx.x * 256 + tid) >> 5;
    int lane = tid & 31;
    float4 r = node_row(reinterpret_cast<const uint2*>(hs), bias, w, lane);

    int g = __ldg(&batch[w]);
    atomicAdd(&accsm[g * H + lane * 4 + 0], r.x);
    atomicAdd(&accsm[g * H + lane * 4 + 1], r.y);
    atomicAdd(&accsm[g * H + lane * 4 + 2], r.z);
    atomicAdd(&accsm[g * H + lane * 4 + 3], r.w);
    if (lane == 0) atomicAdd(&cntsm[g], 1.0f);
    __syncthreads();

    for (int i = tid; i < G * H; i += 256)
        if (accsm[i] != 0.f) atomicAdd(&g_pool[i], accsm[i]);
    if (tid < G && cntsm[tid] != 0.f) atomicAdd(&g_cntf[tid], cntsm[tid]);
}

// ======================= head =======================

__global__ void head_kernel(const float* __restrict__ Wlin, const float* __restrict__ blin,
                            float* __restrict__ out) {
    int warp = threadIdx.x >> 5, lane = threadIdx.x & 31;
    if (warp >= G * C) return;
    int g = warp >> 1, c = warp & 1;
    float s = 0.f;
    for (int d = lane; d < H; d += 32)
        s += g_pool[g * H + d] * Wlin[d * C + c];
    #pragma unroll
    for (int o = 16; o; o >>= 1) s += __shfl_xor_sync(0xffffffff, s, o);
    if (lane == 0) out[g * C + c] = s / fmaxf(g_cntf[g], 1.0f) + blin[c];
}

} // namespace

extern "C" void kernel_launch(void* const* d_in, const int* in_sizes, int n_in,
                              void* d_out, int out_size) {
    const float* x    = (const float*)d_in[0];
    const int*   ei   = (const int*)  d_in[1];
    const int*   bat  = (const int*)  d_in[2];
    const float* W1   = (const float*)d_in[3];
    const float* b1   = (const float*)d_in[4];
    const float* W2   = (const float*)d_in[5];
    const float* b2   = (const float*)d_in[6];
    const float* Wlin = (const float*)d_in[7];
    const float* blin = (const float*)d_in[8];
    float* out = (float*)d_out;
    const int* src = ei;
    const int* dst = ei + E;

    __half *p_w2t, *p_hs, *p_hf;
    cudaGetSymbolAddress((void**)&p_w2t, g_w2t);
    cudaGetSymbolAddress((void**)&p_hs,  g_hs);
    cudaGetSymbolAddress((void**)&p_hf,  g_hf);

    cudaFuncSetAttribute(gemm_t32<IN>, cudaFuncAttributeMaxDynamicSharedMemorySize, (int)T32_SMEM);
    cudaFuncSetAttribute(gemm_f16<H>,  cudaFuncAttributeMaxDynamicSharedMemorySize, (int)F16_SMEM);

    static cudaStream_t s2 = nullptr;
    static cudaEvent_t ev_fork = nullptr, ev_join = nullptr;
    if (!s2) {
        cudaStreamCreateWithFlags(&s2, cudaStreamNonBlocking);
        cudaEventCreateWithFlags(&ev_fork, cudaEventDisableTiming);
        cudaEventCreateWithFlags(&ev_join, cudaEventDisableTiming);
    }

    const int gemm_grid = (N + 127) / 128;       // 391
    const int agg_grid  = (N * 32) / 256;        // 6250
    const int nthr_grid = (N + 255) / 256;
    const int e_grid    = (E + 255) / 256;

    // ---- fork: CSR build + w2 convert + pool zero on side stream; gemm1 on main ----
    cudaEventRecord(ev_fork, 0);
    cudaStreamWaitEvent(s2, ev_fork, 0);

    count_kernel<<<e_grid, 256, 0, s2>>>(dst);                      // 0
    scanA_kernel<<<NB_SCAN, 256, 0, s2>>>();                        // 1
    scanB_kernel<<<1, 256, 0, s2>>>();                              // 2
    gemm_t32<IN><<<gemm_grid, 256, T32_SMEM>>>(x, W1, p_hs);        // 3 (main, ncu)
    scanCD_kernel<<<nthr_grid, 256, 0, s2>>>();                     // 4
    fill_kernel<<<e_grid, 256, 0, s2>>>(src, dst);                  // 5
    cvt_w2_kernel<<<(H * H + 255) / 256, 256, 0, s2>>>(W2);         // 6
    zero_pool_kernel<<<(G * H + 255) / 256, 256, 0, s2>>>();        // 7
    cudaEventRecord(ev_join, s2);

    // ---- join ----
    cudaStreamWaitEvent(0, ev_join, 0);

    // ---- layer 1 agg (fp16 out), fp16 layer 2, fused pool, head ----
    agg_kernel<<<agg_grid, 256>>>(p_hs, b1, p_hf);
    gemm_f16<H><<<gemm_grid, 256, F16_SMEM>>>(p_hf, p_w2t, p_hs);
    agg_pool_kernel<<<agg_grid, 256>>>(p_hs, b2, bat);
    head_kernel<<<1, G * C * 32>>>(Wlin, blin, out);
}